// round 1
// baseline (speedup 1.0000x reference)
#include <cuda_runtime.h>
#include <math.h>
#include <float.h>

// Fixed capacities for this problem instance (B=32, N=300, M=60, L=5, C=1000)
#define CAP_B 32
#define CAP_N 300
#define CAP_M 60
#define HTHREADS 320
#define BCE_CAP_BLOCKS 1024

// ---------------- device scratch (no allocations allowed) ----------------
__device__ float  g_cost[CAP_B * CAP_M * CAP_N];   // [b][t][j] f32 cost
__device__ int    g_assign[CAP_B * CAP_M];         // hungarian row r -> pred index
__device__ int    g_vid[CAP_B * CAP_M];            // hungarian row r -> target index
__device__ int    g_k[CAP_B];                      // valid targets per batch
__device__ float  g_obj_t[CAP_B * CAP_N];          // objectness targets
__device__ double g_cls[CAP_B];                    // per-batch cls loss
__device__ double g_pair[CAP_B * 4];               // per-batch {bbox, giou, aux_bbox, aux_giou}
__device__ double g_bce[BCE_CAP_BLOCKS * 2];       // per-block {main, aux} bce partials

// ---------------- helpers ----------------
__device__ __forceinline__ float giou_f(
    float ax0, float ay0, float ax1, float ay1,
    float bx0, float by0, float bx1, float by1)
{
    const float EPS = 1e-7f;
    float area_a = (ax1 - ax0) * (ay1 - ay0);
    float area_b = (bx1 - bx0) * (by1 - by0);
    float ltx = fmaxf(ax0, bx0), lty = fmaxf(ay0, by0);
    float rbx = fminf(ax1, bx1), rby = fminf(ay1, by1);
    float wx = fmaxf(rbx - ltx, 0.0f), wy = fmaxf(rby - lty, 0.0f);
    float inter = wx * wy;
    float uni = area_a + area_b - inter;
    float iou = inter / (uni + EPS);
    float ex = fmaxf(fmaxf(ax1, bx1) - fminf(ax0, bx0), 0.0f);
    float ey = fmaxf(fmaxf(ay1, by1) - fminf(ay0, by0), 0.0f);
    float enc = ex * ey;
    return iou - (enc - uni) / (enc + EPS);
}

__device__ __forceinline__ float giou_cxcywh(float4 p, float4 q)
{
    return giou_f(p.x - p.z * 0.5f, p.y - p.w * 0.5f, p.x + p.z * 0.5f, p.y + p.w * 0.5f,
                  q.x - q.z * 0.5f, q.y - q.w * 0.5f, q.x + q.z * 0.5f, q.y + q.w * 0.5f);
}

__device__ __forceinline__ float l1_cxcywh(float4 p, float4 q)
{
    return fabsf(p.x - q.x) + fabsf(p.y - q.y) + fabsf(p.z - q.z) + fabsf(p.w - q.w);
}

__device__ __forceinline__ float bce_f(float x, float t)
{
    return fmaxf(x, 0.0f) - x * t + log1pf(expf(-fabsf(x)));
}

// ---------------- kernels ----------------

__global__ void init_kernel(int bn)
{
    int idx = blockIdx.x * blockDim.x + threadIdx.x;
    if (idx < bn) g_obj_t[idx] = 0.0f;
    if (idx < BCE_CAP_BLOCKS * 2) g_bce[idx] = 0.0;
}

// cost[b][t][j] = 5 * L1 - 2 * GIoU
__global__ void cost_kernel(const float4* __restrict__ pred,
                            const float4* __restrict__ tgt,
                            int B, int N, int M)
{
    int idx = blockIdx.x * blockDim.x + threadIdx.x;
    int total = B * M * N;
    if (idx >= total) return;
    int j = idx % N;
    int t = (idx / N) % M;
    int b = idx / (N * M);
    float4 p = pred[b * N + j];
    float4 q = tgt[b * M + t];
    float l1 = l1_cxcywh(p, q);
    float gi = giou_cxcywh(p, q);
    g_cost[idx] = 5.0f * l1 - 2.0f * gi;
}

// One block per batch. JV shortest augmenting path in double precision,
// k rows (valid targets) x N columns (predictions). Lowest-index tie-break
// to match np.argmin.
__global__ void hungarian_kernel(const float* __restrict__ mask, int B, int N, int M)
{
    int b = blockIdx.x;
    int tid = threadIdx.x;
    int lane = tid & 31, wid = tid >> 5;
    const int NW = HTHREADS / 32;

    __shared__ double u_sh[CAP_M + 1];
    __shared__ double v_sh[CAP_N + 1];
    __shared__ double minv_sh[CAP_N + 1];
    __shared__ int way_sh[CAP_N + 1];
    __shared__ int p_sh[CAP_N + 1];
    __shared__ int used_sh[CAP_N + 1];
    __shared__ int vid_sh[CAP_M];
    __shared__ double red_val[NW];
    __shared__ int red_idx[NW];
    __shared__ double s_delta;
    __shared__ int s_jbest;
    __shared__ int s_k;

    // build valid-target list (serial, M<=60, exactness over speed)
    if (tid == 0) {
        int k = 0;
        for (int m = 0; m < M; m++)
            if (mask[b * M + m] > 0.5f) vid_sh[k++] = m;
        s_k = k;
        g_k[b] = k;
    }
    for (int j = tid; j <= N; j += HTHREADS) {
        v_sh[j] = 0.0;
        p_sh[j] = 0;
        way_sh[j] = 0;
    }
    if (tid <= M) u_sh[tid] = 0.0;
    __syncthreads();
    int k = s_k;
    const float* cb = g_cost + (size_t)b * M * N;

    for (int i = 1; i <= k; i++) {
        for (int j = tid; j <= N; j += HTHREADS) {
            minv_sh[j] = INFINITY;
            used_sh[j] = 0;
        }
        if (tid == 0) p_sh[0] = i;
        __syncthreads();
        int j0 = 0;
        while (true) {
            if (tid == 0) used_sh[j0] = 1;
            __syncthreads();
            int i0 = p_sh[j0];
            double ui0 = u_sh[i0];
            const float* crow = cb + (size_t)vid_sh[i0 - 1] * N;

            double val = INFINITY;
            int idx = N + 1;
            if (tid >= 1 && tid <= N && !used_sh[tid]) {
                double cur = (double)crow[tid - 1] - ui0 - v_sh[tid];
                double mv = minv_sh[tid];
                if (cur < mv) {
                    mv = cur;
                    minv_sh[tid] = cur;
                    way_sh[tid] = j0;
                }
                val = mv;
                idx = tid;
            }
            // warp argmin (lowest index on ties)
            #pragma unroll
            for (int off = 16; off; off >>= 1) {
                double ov = __shfl_down_sync(0xffffffffu, val, off);
                int oi = __shfl_down_sync(0xffffffffu, idx, off);
                if (ov < val || (ov == val && oi < idx)) { val = ov; idx = oi; }
            }
            if (lane == 0) { red_val[wid] = val; red_idx[wid] = idx; }
            __syncthreads();
            if (wid == 0) {
                val = (lane < NW) ? red_val[lane] : INFINITY;
                idx = (lane < NW) ? red_idx[lane] : N + 1;
                #pragma unroll
                for (int off = 16; off; off >>= 1) {
                    double ov = __shfl_down_sync(0xffffffffu, val, off);
                    int oi = __shfl_down_sync(0xffffffffu, idx, off);
                    if (ov < val || (ov == val && oi < idx)) { val = ov; idx = oi; }
                }
                if (lane == 0) { s_delta = val; s_jbest = idx; }
            }
            __syncthreads();
            double delta = s_delta;
            j0 = s_jbest;
            // potential update (distinct rows per used column -> no conflicts)
            if (tid <= N) {
                if (used_sh[tid]) {
                    u_sh[p_sh[tid]] += delta;
                    v_sh[tid] -= delta;
                } else {
                    minv_sh[tid] -= delta;
                }
            }
            __syncthreads();
            if (p_sh[j0] == 0) break;
        }
        // augment along alternating path
        if (tid == 0) {
            int jj = j0;
            while (jj) {
                int j1 = way_sh[jj];
                p_sh[jj] = p_sh[j1];
                jj = j1;
            }
        }
        __syncthreads();
    }

    for (int j = 1 + tid; j <= N; j += HTHREADS) {
        if (p_sh[j] != 0) g_assign[b * M + (p_sh[j] - 1)] = j - 1;
        // row r (target vid_sh[r]) matched to pred j-1
    }
    if (tid < M) g_vid[b * M + tid] = vid_sh[tid];
}

__global__ void cls_kernel(const float* __restrict__ logits,
                           const int* __restrict__ label, int B, int C)
{
    int b = blockIdx.x, tid = threadIdx.x;
    __shared__ float sred[256];
    const float* x = logits + (size_t)b * C;
    float m = -FLT_MAX;
    for (int c = tid; c < C; c += 256) m = fmaxf(m, x[c]);
    sred[tid] = m;
    __syncthreads();
    for (int off = 128; off; off >>= 1) {
        if (tid < off) sred[tid] = fmaxf(sred[tid], sred[tid + off]);
        __syncthreads();
    }
    m = sred[0];
    __syncthreads();
    float s = 0.0f;
    for (int c = tid; c < C; c += 256) s += expf(x[c] - m);
    sred[tid] = s;
    __syncthreads();
    for (int off = 128; off; off >>= 1) {
        if (tid < off) sred[tid] += sred[tid + off];
        __syncthreads();
    }
    if (tid == 0) {
        float lse = m + logf(sred[0]);
        g_cls[b] = (double)(lse - x[label[b]]);
    }
}

// Per matched pair: L1 + (1-GIoU) for main and aux layers; scatter obj targets.
__global__ void pairs_kernel(const float4* __restrict__ pred,
                             const float4* __restrict__ tgt,
                             const float4* __restrict__ aux_pred,
                             int B, int N, int M, int L)
{
    int b = blockIdx.x, t = threadIdx.x;  // blockDim = 64
    __shared__ double red[64 * 4];
    double dbb = 0.0, dgi = 0.0, dab = 0.0, dag = 0.0;
    int k = g_k[b];
    if (t < k) {
        int pj = g_assign[b * M + t];
        int tj = g_vid[b * M + t];
        float4 p = pred[b * N + pj];
        float4 q = tgt[b * M + tj];
        dbb = (double)l1_cxcywh(p, q);
        dgi = (double)(1.0f - giou_cxcywh(p, q));
        g_obj_t[b * N + pj] = 1.0f;
        for (int l = 0; l < L; l++) {
            float4 a = aux_pred[((size_t)l * B + b) * N + pj];
            dab += (double)l1_cxcywh(a, q);
            dag += (double)(1.0f - giou_cxcywh(a, q));
        }
    }
    red[t] = dbb; red[64 + t] = dgi; red[128 + t] = dab; red[192 + t] = dag;
    __syncthreads();
    for (int off = 32; off; off >>= 1) {
        if (t < off) {
            red[t] += red[t + off];
            red[64 + t] += red[64 + t + off];
            red[128 + t] += red[128 + t + off];
            red[192 + t] += red[192 + t + off];
        }
        __syncthreads();
    }
    if (t == 0) {
        g_pair[b * 4 + 0] = red[0];
        g_pair[b * 4 + 1] = red[64];
        g_pair[b * 4 + 2] = red[128];
        g_pair[b * 4 + 3] = red[192];
    }
}

__global__ void bce_kernel(const float* __restrict__ obj,
                           const float* __restrict__ aux_obj,
                           int B, int N, int L)
{
    int tid = threadIdx.x;
    int idx = blockIdx.x * blockDim.x + tid;
    int main_total = B * N;
    int total = main_total * (1 + L);
    double vm = 0.0, va = 0.0;
    if (idx < total) {
        if (idx < main_total) {
            vm = (double)bce_f(obj[idx], g_obj_t[idx]);
        } else {
            int a = idx - main_total;
            va = (double)bce_f(aux_obj[a], g_obj_t[a % main_total]);
        }
    }
    __shared__ double rm[256];
    __shared__ double ra[256];
    rm[tid] = vm;
    ra[tid] = va;
    __syncthreads();
    for (int off = 128; off; off >>= 1) {
        if (tid < off) { rm[tid] += rm[tid + off]; ra[tid] += ra[tid + off]; }
        __syncthreads();
    }
    if (tid == 0) {
        g_bce[blockIdx.x * 2 + 0] = rm[0];
        g_bce[blockIdx.x * 2 + 1] = ra[0];
    }
}

__global__ void final_kernel(float* __restrict__ out, int B, int N, int L, int nbce)
{
    double nb = 0.0;
    for (int b = 0; b < B; b++) nb += (double)g_k[b];
    if (nb < 1.0) nb = 1.0;
    double cls = 0.0;
    for (int b = 0; b < B; b++) cls += g_cls[b];
    double bbox = 0.0, gi = 0.0, ab = 0.0, ag = 0.0;
    for (int b = 0; b < B; b++) {
        bbox += g_pair[b * 4 + 0];
        gi   += g_pair[b * 4 + 1];
        ab   += g_pair[b * 4 + 2];
        ag   += g_pair[b * 4 + 3];
    }
    double objs = 0.0, aobj = 0.0;
    for (int i = 0; i < nbce; i++) {
        objs += g_bce[2 * i + 0];
        aobj += g_bce[2 * i + 1];
    }
    double BN = (double)B * (double)N;
    double total = cls / (double)B
                 + 5.0 * bbox / nb
                 + 2.0 * gi / nb
                 + objs / BN
                 + (5.0 * ab / nb + 2.0 * ag / nb + aobj / BN) * 0.5 / (double)L;
    out[0] = (float)total;
}

// ---------------- launch ----------------
extern "C" void kernel_launch(void* const* d_in, const int* in_sizes, int n_in,
                              void* d_out, int out_size)
{
    const float* cls      = (const float*)d_in[0];
    const int*   label    = (const int*)d_in[1];
    const float* pred     = (const float*)d_in[2];
    const float* obj      = (const float*)d_in[3];
    const float* tgt      = (const float*)d_in[4];
    const float* mask     = (const float*)d_in[5];
    const float* aux_pred = (const float*)d_in[6];
    const float* aux_obj  = (const float*)d_in[7];

    int B = in_sizes[1];
    int C = in_sizes[0] / B;
    int N = in_sizes[3] / B;
    int M = in_sizes[5] / B;
    int L = in_sizes[6] / (B * N * 4);
    float* out = (float*)d_out;

    init_kernel<<<(B * N + 255) / 256 + 2, 256>>>(B * N);
    {
        int tot = B * M * N;
        cost_kernel<<<(tot + 255) / 256, 256>>>((const float4*)pred, (const float4*)tgt, B, N, M);
    }
    hungarian_kernel<<<B, HTHREADS>>>(mask, B, N, M);
    cls_kernel<<<B, 256>>>(cls, label, B, C);
    pairs_kernel<<<B, 64>>>((const float4*)pred, (const float4*)tgt,
                            (const float4*)aux_pred, B, N, M, L);
    int bce_total = B * N * (1 + L);
    int nbce = (bce_total + 255) / 256;
    bce_kernel<<<nbce, 256>>>(obj, aux_obj, B, N, L);
    final_kernel<<<1, 1>>>(out, B, N, L, nbce);
}